// round 6
// baseline (speedup 1.0000x reference)
#include <cuda_runtime.h>
#include <math.h>

#define B_       16
#define HDIM     256
#define WDIM     256
#define C_       64
#define HW       (HDIM * WDIM)            // 65536
#define CONV_NUM 7

#define BLK_PER_IMG 64                    // blocks per image
#define NGROUP      2                     // images processed in 2 temporal groups
#define IMG_PER_G   (B_ / NGROUP)         // 8 images per group (134 MB, ~L2-sized)
#define GRID_       (IMG_PER_G * BLK_PER_IMG)   // 512 blocks
#define PIX_PER_BLK (HW / BLK_PER_IMG)    // 1024 pixels
#define ITERS       (PIX_PER_BLK * (C_/4) / 256) // 64 float4-loads per thread

// Scratch (allocation-free rule: __device__ globals)
__device__ float4 g_pmax[B_ * BLK_PER_IMG * (C_ / 4)];   // 256 KB
__device__ float4 g_psum[B_ * BLK_PER_IMG * (C_ / 4)];   // 256 KB
__device__ float  g_scores[B_ * C_];                     // 4 KB
__device__ int    g_counter[B_];
__device__ volatile int g_flag[B_];

// ---------------------------------------------------------------------------
__global__ void reset_kernel()
{
    int t = threadIdx.x;
    if (t < B_) { g_counter[t] = 0; g_flag[t] = 0; }
}

// ---------------------------------------------------------------------------
// Persistent fused kernel. grid GRID_ (512), block 256.
// For each of 2 groups: reduce own chunk -> image sync (last block runs MLP)
// -> scale own chunk (reverse order, L2-resident reads).
// ---------------------------------------------------------------------------
__global__ __launch_bounds__(256) void fused_kernel(const float4* __restrict__ feats4,
                                                    float4* __restrict__ out4,
                                                    const float* __restrict__ W1,
                                                    const float* __restrict__ b1,
                                                    const float* __restrict__ a1)
{
    const int tid  = threadIdx.x;
    const int lane = tid & 15;            // channel group (float4)

    __shared__ float4 smax[256];
    __shared__ float4 ssum[256];
    __shared__ float  smx[C_];
    __shared__ float  sma[C_];

    for (int g = 0; g < NGROUP; g++) {
        const int b = g * IMG_PER_G + (int)(blockIdx.x / BLK_PER_IMG);
        const int p = (int)(blockIdx.x % BLK_PER_IMG);

        const float4* src = feats4 + ((size_t)b * HW + (size_t)p * PIX_PER_BLK) * (C_ / 4);
        float4*       dst = out4   + ((size_t)b * HW + (size_t)p * PIX_PER_BLK) * (C_ / 4);

        // ---- Phase 1: chunk reduce (default cache policy: retain in L2) ----
        float4 vmax = make_float4(-INFINITY, -INFINITY, -INFINITY, -INFINITY);
        float4 vsum = make_float4(0.f, 0.f, 0.f, 0.f);

        #pragma unroll 8
        for (int i = 0; i < ITERS; i++) {
            float4 v = src[i * 256 + tid];           // linear
            vmax.x = fmaxf(vmax.x, v.x); vsum.x += v.x;
            vmax.y = fmaxf(vmax.y, v.y); vsum.y += v.y;
            vmax.z = fmaxf(vmax.z, v.z); vsum.z += v.z;
            vmax.w = fmaxf(vmax.w, v.w); vsum.w += v.w;
        }

        smax[tid] = vmax;
        ssum[tid] = vsum;
        __syncthreads();

        if (tid < 16) {
            float4 m = smax[tid];
            float4 s = ssum[tid];
            #pragma unroll
            for (int j = 1; j < 16; j++) {
                float4 m2 = smax[tid + 16 * j];
                float4 s2 = ssum[tid + 16 * j];
                m.x = fmaxf(m.x, m2.x); s.x += s2.x;
                m.y = fmaxf(m.y, m2.y); s.y += s2.y;
                m.z = fmaxf(m.z, m2.z); s.z += s2.z;
                m.w = fmaxf(m.w, m2.w); s.w += s2.w;
            }
            g_pmax[(b * BLK_PER_IMG + p) * 16 + tid] = m;
            g_psum[(b * BLK_PER_IMG + p) * 16 + tid] = s;
        }
        // Writers' stores must be device-visible before the counter publish:
        // ALL threads fence, then sync, then thread 0 bumps the counter.
        __threadfence();
        __syncthreads();

        // ---- Phase 2: image sync; last-arriving block finalizes + MLP ----
        __shared__ int s_last;
        if (tid == 0) {
            s_last = (atomicAdd(&g_counter[b], 1) == BLK_PER_IMG - 1);
        }
        __syncthreads();

        if (s_last) {
            // finalize reduction + MLP; all 256 threads participate in syncs,
            // only c = tid < 64 carries data.
            const int c = tid;
            float xm = 0.f, xa = 0.f;
            if (c < C_) {
                const float* pmax = (const float*)g_pmax;
                const float* psum = (const float*)g_psum;
                float m = -INFINITY, s = 0.f;
                #pragma unroll 4
                for (int q = 0; q < BLK_PER_IMG; q++) {
                    m = fmaxf(m, pmax[(b * BLK_PER_IMG + q) * C_ + c]);
                    s += psum[(b * BLK_PER_IMG + q) * C_ + c];
                }
                xm = m;
                xa = s * (1.f / (float)HW);
            }

            for (int k = 0; k < CONV_NUM; k++) {
                __syncthreads();
                if (c < C_) { smx[c] = xm; sma[c] = xa; }
                __syncthreads();
                if (c < C_) {
                    const float* Wk = W1 + (size_t)k * C_ * C_ + (size_t)c * C_;
                    float bias  = b1[k * C_ + c];
                    float alpha = a1[k];
                    float ym = bias, ya = bias;
                    #pragma unroll
                    for (int d = 0; d < C_; d++) {
                        float w = Wk[d];
                        ym += smx[d] * w;
                        ya += sma[d] * w;
                    }
                    ym = (ym >= 0.f ? ym : alpha * ym) + xm;
                    ya = (ya >= 0.f ? ya : alpha * ya) + xa;
                    xm = ym; xa = ya;
                }
            }
            if (c < C_) {
                float z = xm + xa;
                g_scores[b * C_ + c] = 1.f / (1.f + expf(-z));
            }
            // Score writers fence, sync, then thread 0 raises the flag.
            __threadfence();
            __syncthreads();
            if (tid == 0) {
                g_flag[b] = 1;
            }
        }

        // ---- Phase 3: wait for scores ----
        if (tid == 0) {
            while (g_flag[b] == 0) { __nanosleep(200); }
        }
        __syncthreads();
        __threadfence();   // acquire side of the flag handshake

        const float4* sc4 = (const float4*)g_scores;
        float4 s = __ldg(&sc4[b * 16 + lane]);

        // ---- Phase 4: scale own chunk, REVERSE order (most-recent lines
        // first, still L2/L1 resident). Streaming hints both directions. ----
        #pragma unroll 1
        for (int jb = ITERS - 8; jb >= 0; jb -= 8) {
            float4 v[8];
            #pragma unroll
            for (int k = 0; k < 8; k++)
                v[k] = __ldcs(&src[(jb + k) * 256 + tid]);
            #pragma unroll
            for (int k = 0; k < 8; k++) {
                v[k].x *= s.x; v[k].y *= s.y; v[k].z *= s.z; v[k].w *= s.w;
                __stcs(&dst[(jb + k) * 256 + tid], v[k]);
            }
        }
        __syncthreads();   // keep block phases aligned before next group
    }
}

// ---------------------------------------------------------------------------
extern "C" void kernel_launch(void* const* d_in, const int* in_sizes, int n_in,
                              void* d_out, int out_size)
{
    const float4* feats4 = (const float4*)d_in[0];
    const float*  W1     = (const float*)d_in[1];
    const float*  b1     = (const float*)d_in[2];
    const float*  a1     = (const float*)d_in[3];
    float4* out4 = (float4*)d_out;

    reset_kernel<<<1, 32>>>();
    fused_kernel<<<GRID_, 256>>>(feats4, out4, W1, b1, a1);

    (void)in_sizes; (void)n_in; (void)out_size;
}